// round 6
// baseline (speedup 1.0000x reference)
#include <cuda_runtime.h>
#include <math_constants.h>

#define BB 2
#define NN 32768
#define MM 4096
#define M2 (MM / 2)
#define CC 128
#define OUTC 128
#define INC 131
#define HPAD 132

typedef unsigned long long ull;

// ---------------------------------------------------------------------------
// Scratch (__device__ globals: allocation-free)
// ---------------------------------------------------------------------------
__device__ __align__(16) float g_w1q[33 * 128 * 4];  // [kq][o][4] permuted w1
__device__ __align__(16) float g_w2q[32 * 128 * 4];  // [kq][o][4] w2
__device__ int g_idx[BB * NN * 3];

// ---------------------------------------------------------------------------
// f32x2 helpers (FFMA2 is PTX-only)
// ---------------------------------------------------------------------------
__device__ __forceinline__ ull fma2(ull a, ull b, ull c) {
    ull d;
    asm("fma.rn.f32x2 %0, %1, %2, %3;" : "=l"(d) : "l"(a), "l"(b), "l"(c));
    return d;
}
__device__ __forceinline__ ull pack2(float a, float b) {
    ull r;
    asm("mov.b64 %0, {%1, %2};" : "=l"(r)
        : "r"(__float_as_uint(a)), "r"(__float_as_uint(b)));
    return r;
}
__device__ __forceinline__ float2 unpack2(ull v) {
    unsigned int lo, hi;
    asm("mov.b64 {%0, %1}, %2;" : "=r"(lo), "=r"(hi) : "l"(v));
    return make_float2(__uint_as_float(lo), __uint_as_float(hi));
}

// strict-< top-3 insertion (preserves jax top_k tie semantics)
#define INSERT3(val, jj, m0, m1, m2, i0, i1, i2)                    \
    do {                                                            \
        float _t = (val); int _j = (jj);                            \
        if (_t < m2) {                                              \
            if (_t < m1) {                                          \
                m2 = m1; i2 = i1;                                   \
                if (_t < m0) { m1 = m0; i1 = i0; m0 = _t; i0 = _j; }\
                else         { m1 = _t; i1 = _j; }                  \
            } else { m2 = _t; i2 = _j; }                            \
        }                                                           \
    } while (0)

// ---------------------------------------------------------------------------
// Kernel 1: kNN (blocks 0..511) + weight prep (blocks 512..576)
//   knn blocks: 128 threads, 1 query/thread (128 queries/block)
//   hot loop: chunks of 8 j2-pairs, tree-min screen, one branch/chunk
// ---------------------------------------------------------------------------
#define KNN_BLOCKS 512
#define W1_W (33 * 128)
#define W2_W (32 * 128)
#define WPREP_ITEMS (W1_W + W2_W)           // 8320
#define WPREP_BLOCKS (WPREP_ITEMS / 128)    // 65

__global__ void __launch_bounds__(128) knn_prep_kernel(
    const float* __restrict__ x, const float* __restrict__ sx,
    const float* __restrict__ w1, const float* __restrict__ w2) {

    if (blockIdx.x >= KNN_BLOCKS) {
        // ---- weight prep path ----
        int i = (blockIdx.x - KNN_BLOCKS) * 128 + threadIdx.x;
        if (i < W1_W) {
            int kq = i >> 7, o = i & 127;
            float v[4];
#pragma unroll
            for (int q = 0; q < 4; q++) {
                int k = kq * 4 + q;
                if (k < 128)      v[q] = w1[o * INC + 3 + k];
                else if (k < 131) v[q] = w1[o * INC + (k - 128)];
                else              v[q] = 0.f;
            }
            *(float4*)&g_w1q[i * 4] = make_float4(v[0], v[1], v[2], v[3]);
        } else {
            int t = i - W1_W;
            int kq = t >> 7, o = t & 127;
            const float* wr = w2 + o * 128 + kq * 4;
            *(float4*)&g_w2q[t * 4] = make_float4(wr[0], wr[1], wr[2], wr[3]);
        }
        return;
    }

    // ---- knn path ----
    extern __shared__ float4 sm4[];
    float4* skA = sm4;        // (-2sx_j,-2sx_j1,-2sy_j,-2sy_j1)  32KB
    float4* skB = sm4 + M2;   // (-2sz_j,-2sz_j1,|s_j|^2,|s_j1|^2) 32KB

    const int q0  = blockIdx.x * 128;
    const int b   = q0 / NN;
    const int tid = threadIdx.x;

    // build paired keys from sx
    const float* sxb = sx + (size_t)b * MM * 3;
    for (int j2 = tid; j2 < M2; j2 += 128) {
        const float* p = sxb + (size_t)j2 * 6;
        float a0 = p[0], a1 = p[1], a2 = p[2];
        float c0 = p[3], c1 = p[4], c2 = p[5];
        skA[j2] = make_float4(-2.f * a0, -2.f * c0, -2.f * a1, -2.f * c1);
        skB[j2] = make_float4(-2.f * a2, -2.f * c2,
                              a0 * a0 + a1 * a1 + a2 * a2,
                              c0 * c0 + c1 * c1 + c2 * c2);
    }
    __syncthreads();

    // 1 query per thread
    const int qa = q0 + tid;
    float a0c = x[qa * 3 + 0], a1c = x[qa * 3 + 1], a2c = x[qa * 3 + 2];
    const ull ax0 = pack2(a0c, a0c), ax1 = pack2(a1c, a1c), ax2 = pack2(a2c, a2c);

    float am0 = CUDART_INF_F, am1 = CUDART_INF_F, am2 = CUDART_INF_F;
    int   ai0 = 0, ai1 = 0, ai2 = 0;

    const ulonglong2* A2 = (const ulonglong2*)skA;
    const ulonglong2* B2 = (const ulonglong2*)skB;

#pragma unroll 1
    for (int jc = 0; jc < M2; jc += 8) {
        float2 va[8];
#pragma unroll
        for (int u = 0; u < 8; u++) {
            ulonglong2 A  = A2[jc + u];
            ulonglong2 Bv = B2[jc + u];
            ull da = fma2(Bv.x, ax2, Bv.y);
            da = fma2(A.y, ax1, da);
            da = fma2(A.x, ax0, da);
            va[u] = unpack2(da);
        }
        // tree-min over 16 candidates (depth 4, ILP-friendly)
        float p0m = fminf(fminf(va[0].x, va[0].y), fminf(va[1].x, va[1].y));
        float p1m = fminf(fminf(va[2].x, va[2].y), fminf(va[3].x, va[3].y));
        float p2m = fminf(fminf(va[4].x, va[4].y), fminf(va[5].x, va[5].y));
        float p3m = fminf(fminf(va[6].x, va[6].y), fminf(va[7].x, va[7].y));
        float cma = fminf(fminf(p0m, p1m), fminf(p2m, p3m));

        if (cma < am2) {   // screened: one branch per 16 candidates
#pragma unroll
            for (int u = 0; u < 8; u++) {
                INSERT3(va[u].x, 2 * (jc + u),     am0, am1, am2, ai0, ai1, ai2);
                INSERT3(va[u].y, 2 * (jc + u) + 1, am0, am1, am2, ai0, ai1, ai2);
            }
        }
    }

    g_idx[qa * 3 + 0] = ai0;
    g_idx[qa * 3 + 1] = ai1;
    g_idx[qa * 3 + 2] = ai2;
}

// ---------------------------------------------------------------------------
// Kernel 2: fused gather + MLP, 512 threads, 64-point tile (unchanged)
// ---------------------------------------------------------------------------
__global__ void __launch_bounds__(512, 2) mlp_kernel(
    const float* __restrict__ x, const float* __restrict__ feat,
    const float* __restrict__ b1, const float* __restrict__ b2,
    float* __restrict__ out) {
    extern __shared__ float sm[];
    float* hs = sm;               // [64][132]
    float* t1 = sm + 64 * HPAD;   // [64][132]

    const int tid = threadIdx.x;
    const int oc2 = tid & 63;     // output channels oc2, oc2+64
    const int pg  = tid >> 6;     // 8 point-groups of 8
    const int pb  = pg * 8;
    const int p0  = blockIdx.x * 64;
    const int b   = p0 / NN;
    const int n0  = p0 - b * NN;

    // ---- gather: 16 warps x 4 points, lane = float4 channel chunk ----
    {
        const int wid  = tid >> 5;
        const int lane = tid & 31;
        const float4* F = (const float4*)feat;
#pragma unroll
        for (int t = 0; t < 4; t++) {
            const int pt = wid * 4 + t;
            const int gq = p0 + pt;
            const int j0 = g_idx[gq * 3 + 0];
            const int j1 = g_idx[gq * 3 + 1];
            const int j2 = g_idx[gq * 3 + 2];
            float4 f0 = F[(size_t)(b * MM + j0) * 32 + lane];
            float4 f1 = F[(size_t)(b * MM + j1) * 32 + lane];
            float4 f2 = F[(size_t)(b * MM + j2) * 32 + lane];
            float4 a;
            a.x = (f0.x + f1.x + f2.x) * (1.f / 3.f);
            a.y = (f0.y + f1.y + f2.y) * (1.f / 3.f);
            a.z = (f0.z + f1.z + f2.z) * (1.f / 3.f);
            a.w = (f0.w + f1.w + f2.w) * (1.f / 3.f);
            *(float4*)&hs[pt * HPAD + lane * 4] = a;
            if (lane == 0) {
                *(float4*)&hs[pt * HPAD + 128] =
                    make_float4(x[gq * 3 + 0], x[gq * 3 + 1], x[gq * 3 + 2], 0.f);
            }
        }
    }
    __syncthreads();

    ull accA[8], accB[8];

    // ---- stage 1: t1 = relu(h @ w1^T + b1) ----
    {
#pragma unroll
        for (int p = 0; p < 8; p++) { accA[p] = 0ull; accB[p] = 0ull; }
        const ulonglong2* w1q = (const ulonglong2*)g_w1q;
        for (int kq = 0; kq < 33; kq++) {
            ulonglong2 wA = w1q[kq * 128 + oc2];        // coalesced LDG.128
            ulonglong2 wB = w1q[kq * 128 + oc2 + 64];
            const float* hrow = hs + pb * HPAD + kq * 4;
#pragma unroll
            for (int p = 0; p < 8; p++) {
                ulonglong2 h = *(const ulonglong2*)(hrow + p * HPAD);  // broadcast
                accA[p] = fma2(wA.x, h.x, accA[p]);
                accA[p] = fma2(wA.y, h.y, accA[p]);
                accB[p] = fma2(wB.x, h.x, accB[p]);
                accB[p] = fma2(wB.y, h.y, accB[p]);
            }
        }
        const float biasA = b1[oc2];
        const float biasB = b1[oc2 + 64];
#pragma unroll
        for (int p = 0; p < 8; p++) {
            float2 sA = unpack2(accA[p]);
            float2 sB = unpack2(accB[p]);
            t1[(pb + p) * HPAD + oc2]      = fmaxf(sA.x + sA.y + biasA, 0.f);
            t1[(pb + p) * HPAD + oc2 + 64] = fmaxf(sB.x + sB.y + biasB, 0.f);
        }
    }
    __syncthreads();

    // ---- stage 2: out = t1 @ w2^T + b2 ----
    {
#pragma unroll
        for (int p = 0; p < 8; p++) { accA[p] = 0ull; accB[p] = 0ull; }
        const ulonglong2* w2q = (const ulonglong2*)g_w2q;
        for (int kq = 0; kq < 32; kq++) {
            ulonglong2 wA = w2q[kq * 128 + oc2];
            ulonglong2 wB = w2q[kq * 128 + oc2 + 64];
            const float* trow = t1 + pb * HPAD + kq * 4;
#pragma unroll
            for (int p = 0; p < 8; p++) {
                ulonglong2 h = *(const ulonglong2*)(trow + p * HPAD);
                accA[p] = fma2(wA.x, h.x, accA[p]);
                accA[p] = fma2(wA.y, h.y, accA[p]);
                accB[p] = fma2(wB.x, h.x, accB[p]);
                accB[p] = fma2(wB.y, h.y, accB[p]);
            }
        }
        const float biasA = b2[oc2];
        const float biasB = b2[oc2 + 64];
        float* s_o = hs;   // reuse, stride 129 (conflict-free transpose)
#pragma unroll
        for (int p = 0; p < 8; p++) {
            float2 sA = unpack2(accA[p]);
            float2 sB = unpack2(accB[p]);
            s_o[(pb + p) * 129 + oc2]      = sA.x + sA.y + biasA;
            s_o[(pb + p) * 129 + oc2 + 64] = sB.x + sB.y + biasB;
        }
    }
    __syncthreads();

    // ---- coalesced transposed store: out[b][oc][n0+p] ----
    {
        const float* s_o = hs;
        float* ob = out + (size_t)b * OUTC * NN + n0;
        for (int idx = tid; idx < 128 * 64; idx += 512) {
            const int oc = idx >> 6;
            const int p  = idx & 63;
            ob[(size_t)oc * NN + p] = s_o[p * 129 + oc];
        }
    }
}

// ---------------------------------------------------------------------------
extern "C" void kernel_launch(void* const* d_in, const int* in_sizes, int n_in,
                              void* d_out, int out_size) {
    const float* x   = (const float*)d_in[0];
    const float* sx  = (const float*)d_in[1];
    const float* ft  = (const float*)d_in[2];
    const float* w1  = (const float*)d_in[3];
    const float* b1  = (const float*)d_in[4];
    const float* w2  = (const float*)d_in[5];
    const float* b2  = (const float*)d_in[6];
    float* out = (float*)d_out;

    const int knn_smem = MM * sizeof(float4);            // 64 KB
    const int mlp_smem = 2 * 64 * HPAD * sizeof(float);  // 67.6 KB

    cudaFuncSetAttribute(knn_prep_kernel,
                         cudaFuncAttributeMaxDynamicSharedMemorySize, knn_smem);
    cudaFuncSetAttribute(mlp_kernel,
                         cudaFuncAttributeMaxDynamicSharedMemorySize, mlp_smem);

    knn_prep_kernel<<<KNN_BLOCKS + WPREP_BLOCKS, 128, knn_smem>>>(x, sx, w1, w2);
    mlp_kernel<<<(BB * NN) / 64, 512, mlp_smem>>>(x, ft, b1, b2, out);
}

// round 7
// speedup vs baseline: 1.3018x; 1.3018x over previous
#include <cuda_runtime.h>
#include <math_constants.h>

#define BB 2
#define NN 32768
#define MM 4096
#define M2 (MM / 2)
#define CC 128
#define OUTC 128
#define INC 131
#define HPAD 132

typedef unsigned long long ull;

// ---------------------------------------------------------------------------
// Scratch (__device__ globals: allocation-free). w-arrays padded +1 row for
// unconditional prefetch reads (zero-init, never used in math).
// ---------------------------------------------------------------------------
__device__ __align__(16) float g_w1q[34 * 128 * 4];  // [kq][o][4] permuted w1
__device__ __align__(16) float g_w2q[33 * 128 * 4];  // [kq][o][4] w2
__device__ int g_idx[BB * NN * 3];

// ---------------------------------------------------------------------------
// f32x2 helpers (FFMA2 is PTX-only)
// ---------------------------------------------------------------------------
__device__ __forceinline__ ull fma2(ull a, ull b, ull c) {
    ull d;
    asm("fma.rn.f32x2 %0, %1, %2, %3;" : "=l"(d) : "l"(a), "l"(b), "l"(c));
    return d;
}
__device__ __forceinline__ ull pack2(float a, float b) {
    ull r;
    asm("mov.b64 %0, {%1, %2};" : "=l"(r)
        : "r"(__float_as_uint(a)), "r"(__float_as_uint(b)));
    return r;
}
__device__ __forceinline__ float2 unpack2(ull v) {
    unsigned int lo, hi;
    asm("mov.b64 {%0, %1}, %2;" : "=r"(lo), "=r"(hi) : "l"(v));
    return make_float2(__uint_as_float(lo), __uint_as_float(hi));
}

// branchless strict-< top-3 merge (flat compare-select, no BSSY)
__device__ __forceinline__ void bmerge(float v, int j,
    float& m0, float& m1, float& m2, int& i0, int& i1, int& i2) {
    bool p0 = v < m0, p1 = v < m1, p2 = v < m2;
    float nm2 = p1 ? m1 : (p2 ? v : m2);
    int   ni2 = p1 ? i1 : (p2 ? j : i2);
    float nm1 = p0 ? m0 : (p1 ? v : m1);
    int   ni1 = p0 ? i0 : (p1 ? j : i1);
    float nm0 = p0 ? v : m0;
    int   ni0 = p0 ? j : i0;
    m0 = nm0; m1 = nm1; m2 = nm2;
    i0 = ni0; i1 = ni1; i2 = ni2;
}

// ---------------------------------------------------------------------------
// Kernel 1: kNN (blocks 0..511) + weight prep (blocks 512..576)
//   knn: 128 threads, 1 query/thread, two-pass flag-and-replay
// ---------------------------------------------------------------------------
#define KNN_BLOCKS 512
#define W1_W (33 * 128)
#define W2_W (32 * 128)
#define WPREP_ITEMS (W1_W + W2_W)           // 8320
#define WPREP_BLOCKS (WPREP_ITEMS / 128)    // 65

__global__ void __launch_bounds__(128) knn_prep_kernel(
    const float* __restrict__ x, const float* __restrict__ sx,
    const float* __restrict__ w1, const float* __restrict__ w2) {

    if (blockIdx.x >= KNN_BLOCKS) {
        // ---- weight prep path ----
        int i = (blockIdx.x - KNN_BLOCKS) * 128 + threadIdx.x;
        if (i < W1_W) {
            int kq = i >> 7, o = i & 127;
            float v[4];
#pragma unroll
            for (int q = 0; q < 4; q++) {
                int k = kq * 4 + q;
                if (k < 128)      v[q] = w1[o * INC + 3 + k];
                else if (k < 131) v[q] = w1[o * INC + (k - 128)];
                else              v[q] = 0.f;
            }
            *(float4*)&g_w1q[i * 4] = make_float4(v[0], v[1], v[2], v[3]);
        } else {
            int t = i - W1_W;
            int kq = t >> 7, o = t & 127;
            const float* wr = w2 + o * 128 + kq * 4;
            *(float4*)&g_w2q[t * 4] = make_float4(wr[0], wr[1], wr[2], wr[3]);
        }
        return;
    }

    // ---- knn path ----
    extern __shared__ float4 sm4[];
    float4* skA = sm4;        // (-2sx_j,-2sx_j1,-2sy_j,-2sy_j1)  32KB
    float4* skB = sm4 + M2;   // (-2sz_j,-2sz_j1,|s_j|^2,|s_j1|^2) 32KB

    const int q0  = blockIdx.x * 128;
    const int b   = q0 / NN;
    const int tid = threadIdx.x;

    const float* sxb = sx + (size_t)b * MM * 3;
    for (int j2 = tid; j2 < M2; j2 += 128) {
        const float* p = sxb + (size_t)j2 * 6;
        float a0 = p[0], a1 = p[1], a2 = p[2];
        float c0 = p[3], c1 = p[4], c2 = p[5];
        skA[j2] = make_float4(-2.f * a0, -2.f * c0, -2.f * a1, -2.f * c1);
        skB[j2] = make_float4(-2.f * a2, -2.f * c2,
                              a0 * a0 + a1 * a1 + a2 * a2,
                              c0 * c0 + c1 * c1 + c2 * c2);
    }
    __syncthreads();

    const int qa = q0 + tid;
    const float xc0 = x[qa * 3 + 0];
    const float xc1 = x[qa * 3 + 1];
    const float xc2 = x[qa * 3 + 2];
    const ull ax0 = pack2(xc0, xc0), ax1 = pack2(xc1, xc1), ax2 = pack2(xc2, xc2);

    const ulonglong2* A2 = (const ulonglong2*)skA;
    const ulonglong2* B2 = (const ulonglong2*)skB;

    // ---- pass 1: branchless chunk-min top-3 bound + flag bits ----
    float m0 = CUDART_INF_F, m1 = CUDART_INF_F, m2v = CUDART_INF_F;
    unsigned flags[8];

#pragma unroll
    for (int w8 = 0; w8 < 8; w8++) {
        unsigned fm = 0;
#pragma unroll 1
        for (int cb = 0; cb < 32; cb++) {
            const int jc = w8 * 256 + cb * 8;   // 8 pairs = 16 candidates
            float pmin[8];
#pragma unroll
            for (int u = 0; u < 8; u++) {
                ulonglong2 A  = A2[jc + u];
                ulonglong2 Bv = B2[jc + u];
                ull d = fma2(Bv.x, ax2, Bv.y);
                d = fma2(A.y, ax1, d);
                d = fma2(A.x, ax0, d);
                float2 vv = unpack2(d);
                pmin[u] = fminf(vv.x, vv.y);
            }
            float q01 = fminf(pmin[0], pmin[1]);
            float q23 = fminf(pmin[2], pmin[3]);
            float q45 = fminf(pmin[4], pmin[5]);
            float q67 = fminf(pmin[6], pmin[7]);
            float cmin = fminf(fminf(q01, q23), fminf(q45, q67));

            fm |= (cmin <= m2v) ? (1u << cb) : 0u;
            // top-3 of chunk-mins (upper bound on true 3rd distance)
            float t2 = fmaxf(m1, cmin);
            float t1 = fmaxf(m0, cmin);
            m2v = fminf(m2v, t2);
            m1  = fminf(m1, t1);
            m0  = fminf(m0, cmin);
        }
        flags[w8] = fm;
    }

    // ---- pass 2: replay only flagged chunks, exact branchless merge ----
    float n0 = CUDART_INF_F, n1 = CUDART_INF_F, n2 = CUDART_INF_F;
    int   i0 = 0, i1 = 0, i2 = 0;

#pragma unroll
    for (int w8 = 0; w8 < 8; w8++) {
        unsigned fm = flags[w8];
        while (fm) {
            const int cb = __ffs(fm) - 1;
            fm &= fm - 1;
            const int jc = w8 * 256 + cb * 8;
#pragma unroll
            for (int u = 0; u < 8; u++) {
                ulonglong2 A  = A2[jc + u];
                ulonglong2 Bv = B2[jc + u];
                ull d = fma2(Bv.x, ax2, Bv.y);
                d = fma2(A.y, ax1, d);
                d = fma2(A.x, ax0, d);
                float2 vv = unpack2(d);
                bmerge(vv.x, 2 * (jc + u),     n0, n1, n2, i0, i1, i2);
                bmerge(vv.y, 2 * (jc + u) + 1, n0, n1, n2, i0, i1, i2);
            }
        }
    }

    g_idx[qa * 3 + 0] = i0;
    g_idx[qa * 3 + 1] = i1;
    g_idx[qa * 3 + 2] = i2;
}

// ---------------------------------------------------------------------------
// Kernel 2: fused gather + MLP, 256 threads, 64-point tile
//   thread = (oc4 = tid&31 -> channels {oc4,+32,+64,+96}, pg = tid>>5 -> 8 pts)
//   h LDS warp-uniform broadcast reused by 4 channels; weight prefetch
// ---------------------------------------------------------------------------
__global__ void __launch_bounds__(256, 2) mlp_kernel(
    const float* __restrict__ x, const float* __restrict__ feat,
    const float* __restrict__ b1, const float* __restrict__ b2,
    float* __restrict__ out) {
    extern __shared__ float sm[];
    float* hs = sm;               // [64][132]
    float* t1 = sm + 64 * HPAD;   // [64][132]

    const int tid = threadIdx.x;
    const int oc4 = tid & 31;     // channels oc4, +32, +64, +96
    const int pg  = tid >> 5;     // 8 groups of 8 points (warp-uniform)
    const int pb  = pg * 8;
    const int p0  = blockIdx.x * 64;
    const int b   = p0 / NN;
    const int n0  = p0 - b * NN;

    // ---- gather: 8 warps x 8 points, lane = float4 channel chunk ----
    {
        const int wid  = tid >> 5;
        const int lane = tid & 31;
        const float4* F = (const float4*)feat;
#pragma unroll
        for (int t = 0; t < 8; t++) {
            const int pt = wid * 8 + t;
            const int gq = p0 + pt;
            const int j0 = g_idx[gq * 3 + 0];
            const int j1 = g_idx[gq * 3 + 1];
            const int j2 = g_idx[gq * 3 + 2];
            float4 f0 = F[(size_t)(b * MM + j0) * 32 + lane];
            float4 f1 = F[(size_t)(b * MM + j1) * 32 + lane];
            float4 f2 = F[(size_t)(b * MM + j2) * 32 + lane];
            float4 a;
            a.x = (f0.x + f1.x + f2.x) * (1.f / 3.f);
            a.y = (f0.y + f1.y + f2.y) * (1.f / 3.f);
            a.z = (f0.z + f1.z + f2.z) * (1.f / 3.f);
            a.w = (f0.w + f1.w + f2.w) * (1.f / 3.f);
            *(float4*)&hs[pt * HPAD + lane * 4] = a;
            if (lane == 0) {
                *(float4*)&hs[pt * HPAD + 128] =
                    make_float4(x[gq * 3 + 0], x[gq * 3 + 1], x[gq * 3 + 2], 0.f);
            }
        }
    }
    __syncthreads();

    ull a0[8], a1[8], a2[8], a3[8];

    // ---- stage 1: t1 = relu(h @ w1^T + b1), 33 kq, weight prefetch ----
    {
#pragma unroll
        for (int p = 0; p < 8; p++) { a0[p] = 0; a1[p] = 0; a2[p] = 0; a3[p] = 0; }
        const ulonglong2* w1q = (const ulonglong2*)g_w1q;
        ulonglong2 wA = w1q[oc4];
        ulonglong2 wB = w1q[oc4 + 32];
        ulonglong2 wC = w1q[oc4 + 64];
        ulonglong2 wD = w1q[oc4 + 96];
#pragma unroll 1
        for (int kq = 0; kq < 33; kq++) {
            ulonglong2 nA = w1q[(kq + 1) * 128 + oc4];        // padded row 33
            ulonglong2 nB = w1q[(kq + 1) * 128 + oc4 + 32];
            ulonglong2 nC = w1q[(kq + 1) * 128 + oc4 + 64];
            ulonglong2 nD = w1q[(kq + 1) * 128 + oc4 + 96];
            const float* hrow = hs + pb * HPAD + kq * 4;
#pragma unroll
            for (int p = 0; p < 8; p++) {
                ulonglong2 h = *(const ulonglong2*)(hrow + p * HPAD);  // broadcast
                a0[p] = fma2(wA.x, h.x, a0[p]); a0[p] = fma2(wA.y, h.y, a0[p]);
                a1[p] = fma2(wB.x, h.x, a1[p]); a1[p] = fma2(wB.y, h.y, a1[p]);
                a2[p] = fma2(wC.x, h.x, a2[p]); a2[p] = fma2(wC.y, h.y, a2[p]);
                a3[p] = fma2(wD.x, h.x, a3[p]); a3[p] = fma2(wD.y, h.y, a3[p]);
            }
            wA = nA; wB = nB; wC = nC; wD = nD;
        }
        const float bA = b1[oc4], bB = b1[oc4 + 32];
        const float bC = b1[oc4 + 64], bD = b1[oc4 + 96];
#pragma unroll
        for (int p = 0; p < 8; p++) {
            float2 s0 = unpack2(a0[p]), s1 = unpack2(a1[p]);
            float2 s2 = unpack2(a2[p]), s3 = unpack2(a3[p]);
            float* tr = t1 + (pb + p) * HPAD;
            tr[oc4]      = fmaxf(s0.x + s0.y + bA, 0.f);
            tr[oc4 + 32] = fmaxf(s1.x + s1.y + bB, 0.f);
            tr[oc4 + 64] = fmaxf(s2.x + s2.y + bC, 0.f);
            tr[oc4 + 96] = fmaxf(s3.x + s3.y + bD, 0.f);
        }
    }
    __syncthreads();

    // ---- stage 2: out = t1 @ w2^T + b2, 32 kq ----
    {
#pragma unroll
        for (int p = 0; p < 8; p++) { a0[p] = 0; a1[p] = 0; a2[p] = 0; a3[p] = 0; }
        const ulonglong2* w2q = (const ulonglong2*)g_w2q;
        ulonglong2 wA = w2q[oc4];
        ulonglong2 wB = w2q[oc4 + 32];
        ulonglong2 wC = w2q[oc4 + 64];
        ulonglong2 wD = w2q[oc4 + 96];
#pragma unroll 1
        for (int kq = 0; kq < 32; kq++) {
            ulonglong2 nA = w2q[(kq + 1) * 128 + oc4];        // padded row 32
            ulonglong2 nB = w2q[(kq + 1) * 128 + oc4 + 32];
            ulonglong2 nC = w2q[(kq + 1) * 128 + oc4 + 64];
            ulonglong2 nD = w2q[(kq + 1) * 128 + oc4 + 96];
            const float* trow = t1 + pb * HPAD + kq * 4;
#pragma unroll
            for (int p = 0; p < 8; p++) {
                ulonglong2 h = *(const ulonglong2*)(trow + p * HPAD);
                a0[p] = fma2(wA.x, h.x, a0[p]); a0[p] = fma2(wA.y, h.y, a0[p]);
                a1[p] = fma2(wB.x, h.x, a1[p]); a1[p] = fma2(wB.y, h.y, a1[p]);
                a2[p] = fma2(wC.x, h.x, a2[p]); a2[p] = fma2(wC.y, h.y, a2[p]);
                a3[p] = fma2(wD.x, h.x, a3[p]); a3[p] = fma2(wD.y, h.y, a3[p]);
            }
            wA = nA; wB = nB; wC = nC; wD = nD;
        }
        const float bA = b2[oc4], bB = b2[oc4 + 32];
        const float bC = b2[oc4 + 64], bD = b2[oc4 + 96];
        float* s_o = hs;   // reuse, stride 129 (conflict-free transpose)
#pragma unroll
        for (int p = 0; p < 8; p++) {
            float2 s0 = unpack2(a0[p]), s1 = unpack2(a1[p]);
            float2 s2 = unpack2(a2[p]), s3 = unpack2(a3[p]);
            float* sr = s_o + (pb + p) * 129;
            sr[oc4]      = s0.x + s0.y + bA;
            sr[oc4 + 32] = s1.x + s1.y + bB;
            sr[oc4 + 64] = s2.x + s2.y + bC;
            sr[oc4 + 96] = s3.x + s3.y + bD;
        }
    }
    __syncthreads();

    // ---- coalesced transposed store: out[b][oc][n0+p] ----
    {
        const float* s_o = hs;
        float* ob = out + (size_t)b * OUTC * NN + n0;
        for (int idx = tid; idx < 128 * 64; idx += 256) {
            const int oc = idx >> 6;
            const int p  = idx & 63;
            ob[(size_t)oc * NN + p] = s_o[p * 129 + oc];
        }
    }
}

// ---------------------------------------------------------------------------
extern "C" void kernel_launch(void* const* d_in, const int* in_sizes, int n_in,
                              void* d_out, int out_size) {
    const float* x   = (const float*)d_in[0];
    const float* sx  = (const float*)d_in[1];
    const float* ft  = (const float*)d_in[2];
    const float* w1  = (const float*)d_in[3];
    const float* b1  = (const float*)d_in[4];
    const float* w2  = (const float*)d_in[5];
    const float* b2  = (const float*)d_in[6];
    float* out = (float*)d_out;

    const int knn_smem = MM * sizeof(float4);            // 64 KB
    const int mlp_smem = 2 * 64 * HPAD * sizeof(float);  // 67.6 KB

    cudaFuncSetAttribute(knn_prep_kernel,
                         cudaFuncAttributeMaxDynamicSharedMemorySize, knn_smem);
    cudaFuncSetAttribute(mlp_kernel,
                         cudaFuncAttributeMaxDynamicSharedMemorySize, mlp_smem);

    knn_prep_kernel<<<KNN_BLOCKS + WPREP_BLOCKS, 128, knn_smem>>>(x, sx, w1, w2);
    mlp_kernel<<<(BB * NN) / 64, 256, mlp_smem>>>(x, ft, b1, b2, out);
}